// round 11
// baseline (speedup 1.0000x reference)
#include <cuda_runtime.h>
#include <cuda_fp16.h>
#include <math.h>
#include <stdint.h>

// Problem constants
#define M_TOK   8192
#define D_IN    4096
#define Z_DIM   1024
#define D_OUT   4096
#define CAT_DIM 5120
#define LN_EPS  1e-5f

#define MU_OFF  (M_TOK * (size_t)D_OUT)
#define STD_OFF (MU_OFF + (size_t)M_TOK * Z_DIM)

// Scratch (device globals — allocation-free per harness rules)
__device__ __align__(256) float  g_c[(size_t)M_TOK * Z_DIM];      // pre-LN (fp32)
__device__ __align__(256) __half g_h[(size_t)M_TOK * Z_DIM];      // post LN+tanh (fp16)
__device__ __align__(256) __half g_cat[(size_t)M_TOK * CAT_DIM];  // tanh concat (fp16)
__device__ __align__(256) __half g_x16[(size_t)M_TOK * D_IN];     // x in fp16
// fp16 weights, packed: W1 | W2 | Wmu | Wls | Wzw (Wmu,Wls adjacent => fused)
#define W1_OFF  0
#define W2_OFF  4194304
#define WMU_OFF 5242880
#define WLS_OFF 6291456
#define WZW_OFF 7340032
#define W_TOTAL 28311552
__device__ __align__(256) __half g_w16[(size_t)W_TOTAL];

// ---------------------------------------------------------------------------
// PTX helpers
// ---------------------------------------------------------------------------
__device__ __forceinline__ void cp16(uint32_t dst, const void* src) {
    asm volatile("cp.async.cg.shared.global [%0], [%1], 16;\n" :: "r"(dst), "l"(src));
}
__device__ __forceinline__ void cp_commit() {
    asm volatile("cp.async.commit_group;\n" ::: "memory");
}
__device__ __forceinline__ void cp_wait1() {
    asm volatile("cp.async.wait_group 1;\n" ::: "memory");
}
__device__ __forceinline__ void ldsm4(uint32_t* r, uint32_t addr) {
    asm volatile("ldmatrix.sync.aligned.m8n8.x4.shared.b16 {%0,%1,%2,%3}, [%4];\n"
        : "=r"(r[0]), "=r"(r[1]), "=r"(r[2]), "=r"(r[3]) : "r"(addr));
}
__device__ __forceinline__ void mma_f16(float* d, const uint32_t* a, const uint32_t* b) {
    asm volatile(
        "mma.sync.aligned.m16n8k16.row.col.f32.f16.f16.f32 "
        "{%0,%1,%2,%3}, {%4,%5,%6,%7}, {%8,%9}, {%0,%1,%2,%3};\n"
        : "+f"(d[0]), "+f"(d[1]), "+f"(d[2]), "+f"(d[3])
        : "r"(a[0]), "r"(a[1]), "r"(a[2]), "r"(a[3]), "r"(b[0]), "r"(b[1]));
}

// ---------------------------------------------------------------------------
// fp16 tensor-core GEMM with FRAGMENT DOUBLE-BUFFERING (race-free ordering).
// C[M,N](fp32) = A[M,K](fp16) * B[N,K]^T(fp16) + bias
// Block tile 128x128, BK=32 halfs, 3-stage cp.async (48KB static),
// 256 threads, 8 warps (2M x 4N), warp tile 64x32.
// Per iteration: ldsm(buf1, kt.kk1) ; issue kt+2 ; mma(buf0) ;
//                wait+SYNC (kt+1 visible CTA-wide) ; ldsm(buf0, kt+1.kk0) ;
//                mma(buf1).
// Every smem read happens only after a __syncthreads that follows all
// threads' cp.async.wait_group for that stage (cp.async completion is
// per-thread; visibility requires the barrier).
// mode 0: plain. mode 2: split N at Z_DIM -> C(+biasA) | exp(0.5*(v+biasB))->C2.
// ---------------------------------------------------------------------------
#define GBK 32
#define STAGE_BYTES 16384
#define B_OFF       8192

__global__ void __launch_bounds__(256)
gemm_f16_kernel(const __half* __restrict__ A, const __half* __restrict__ B,
                const float* __restrict__ biasA, const float* __restrict__ biasB,
                float* __restrict__ C, float* __restrict__ C2,
                int M, int N, int K, int mode)
{
    __shared__ __align__(128) char smem[3 * STAGE_BYTES];   // 48 KB

    const int tid  = threadIdx.x;
    const int lane = tid & 31;
    const int warp = tid >> 5;
    const int warp_m = warp & 1;
    const int warp_n = warp >> 1;

    const int bm = blockIdx.y * 128;
    const int bn = blockIdx.x * 128;

    const uint32_t sm_base = (uint32_t)__cvta_generic_to_shared(smem);

    // ---- cp.async mapping: row = tid>>1, chunks (tid&1)*2 + {0,1} (16B = 8 halfs)
    const int ld_row = tid >> 1;
    const int ld_c0  = (tid & 1) * 2;
    const int ld_swz = (ld_row >> 1) & 3;
    const __half* Ag = A + (size_t)(bm + ld_row) * K + ld_c0 * 8;
    const __half* Bg = B + (size_t)(bn + ld_row) * K + ld_c0 * 8;
    uint32_t a_dst[2], b_dst[2];
#pragma unroll
    for (int i = 0; i < 2; i++) {
        uint32_t off = (uint32_t)(ld_row * 64 + (((ld_c0 + i) ^ ld_swz) << 4));
        a_dst[i] = sm_base + off;
        b_dst[i] = sm_base + B_OFF + off;
    }

    // ---- ldmatrix address precompute
    const int sa   = (lane & 7) + ((lane >> 3) & 1) * 8;
    const int hiA  = (lane >> 4) & 1;
    const int aswz = (sa >> 1) & 3;
    uint32_t a_base[4];
#pragma unroll
    for (int mf = 0; mf < 4; mf++)
        a_base[mf] = sm_base + (uint32_t)(warp_m * 64 + mf * 16 + sa) * 64u;

    const int hiB  = (lane >> 3) & 1;
    const int nbr  = ((lane >> 4) & 1) * 8 + (lane & 7);
    const int bswz = (nbr >> 1) & 3;
    uint32_t b_base[2];
#pragma unroll
    for (int p = 0; p < 2; p++)
        b_base[p] = sm_base + B_OFF + (uint32_t)(warp_n * 32 + p * 16 + nbr) * 64u;

    // ---- epilogue routing (split boundary Z_DIM is 128-aligned)
    const float* bp = biasA;
    float* Cp = C;
    int cadj = 0, effN = N, emode = 0;
    if (mode == 2) {
        effN = Z_DIM;
        if (bn >= Z_DIM) { bp = biasB; Cp = C2; cadj = Z_DIM; emode = 1; }
    }

    float bias2[4][2];
#pragma unroll
    for (int nf = 0; nf < 4; nf++) {
        int col = bn - cadj + warp_n * 32 + nf * 8 + (lane & 3) * 2;
        bias2[nf][0] = __ldg(bp + col);
        bias2[nf][1] = __ldg(bp + col + 1);
    }

    float acc[4][4][4];
#pragma unroll
    for (int mf = 0; mf < 4; mf++)
#pragma unroll
        for (int nf = 0; nf < 4; nf++)
#pragma unroll
            for (int r = 0; r < 4; r++) acc[mf][nf][r] = 0.f;

    const int KT = K / GBK;

    // ---- fragment double buffers
    uint32_t afr[2][4][4];
    uint32_t bfr[2][4][2];

    auto load_frags = [&](int buf, uint32_t so, int kk) {
#pragma unroll
        for (int mf = 0; mf < 4; mf++)
            ldsm4(afr[buf][mf], a_base[mf] + so + (uint32_t)(((kk * 2 + hiA) ^ aswz) << 4));
#pragma unroll
        for (int p = 0; p < 2; p++) {
            uint32_t r[4];
            ldsm4(r, b_base[p] + so + (uint32_t)(((kk * 2 + hiB) ^ bswz) << 4));
            bfr[buf][2 * p][0] = r[0]; bfr[buf][2 * p][1] = r[1];
            bfr[buf][2 * p + 1][0] = r[2]; bfr[buf][2 * p + 1][1] = r[3];
        }
    };
    auto mma_all = [&](int buf) {
#pragma unroll
        for (int mf = 0; mf < 4; mf++)
#pragma unroll
            for (int nf = 0; nf < 4; nf++)
                mma_f16(acc[mf][nf], afr[buf][mf], bfr[buf][nf]);
    };

    // ---- prologue: prefetch stages 0,1 ; stage 0 visible ; load first slice
#pragma unroll
    for (int s = 0; s < 2; s++) {
        const __half* ap = Ag + s * GBK;
        const __half* bq = Bg + s * GBK;
        uint32_t so = (uint32_t)s * STAGE_BYTES;
        cp16(a_dst[0] + so, ap);
        cp16(a_dst[1] + so, ap + 8);
        cp16(b_dst[0] + so, bq);
        cp16(b_dst[1] + so, bq + 8);
        cp_commit();
    }
    cp_wait1();            // own stage-0 copies done (1 group may pend)
    __syncthreads();       // CTA-wide visibility of stage 0
    load_frags(0, 0u, 0);  // slice (kt=0, kk=0)

    // ---- main loop
#pragma unroll 1
    for (int kt = 0; kt < KT; kt++) {
        const uint32_t so_cur = (uint32_t)(kt % 3) * STAGE_BYTES;

        // stage kt is synced-visible (prologue or previous iteration)
        load_frags(1, so_cur, 1);          // ldsm in flight...

        // issue stage kt+2 into stage kt-1's slot (reads done before last sync)
        {
            int nxt = kt + 2;
            if (nxt < KT) {
                int sn = nxt % 3;
                const __half* ap = Ag + nxt * GBK;
                const __half* bq = Bg + nxt * GBK;
                uint32_t so = (uint32_t)sn * STAGE_BYTES;
                cp16(a_dst[0] + so, ap);
                cp16(a_dst[1] + so, ap + 8);
                cp16(b_dst[0] + so, bq);
                cp16(b_dst[1] + so, bq + 8);
            }
            cp_commit();
        }

        mma_all(0);                        // ...overlapped by buf0 mma batch

        cp_wait1();                        // own stage kt+1 copies done
        __syncthreads();                   // CTA-wide visibility of stage kt+1

        if (kt + 1 < KT)
            load_frags(0, (uint32_t)((kt + 1) % 3) * STAGE_BYTES, 0);  // in flight...
        mma_all(1);                        // ...overlapped by buf1 mma batch
    }

    // ---- epilogue (fp32 out)
#pragma unroll
    for (int mf = 0; mf < 4; mf++) {
        int r0 = bm + warp_m * 64 + mf * 16 + (lane >> 2);
#pragma unroll
        for (int nf = 0; nf < 4; nf++) {
            int col = bn - cadj + warp_n * 32 + nf * 8 + (lane & 3) * 2;
            float v0 = acc[mf][nf][0] + bias2[nf][0];
            float v1 = acc[mf][nf][1] + bias2[nf][1];
            float v2 = acc[mf][nf][2] + bias2[nf][0];
            float v3 = acc[mf][nf][3] + bias2[nf][1];
            if (emode == 1) {
                v0 = expf(0.5f * v0); v1 = expf(0.5f * v1);
                v2 = expf(0.5f * v2); v3 = expf(0.5f * v3);
            }
            *(float2*)(Cp + (size_t)r0 * effN + col) = make_float2(v0, v1);
            *(float2*)(Cp + (size_t)(r0 + 8) * effN + col) = make_float2(v2, v3);
        }
    }
}

// ---------------------------------------------------------------------------
// x prep: x16 = fp16(x) AND cat[:,Z_DIM:] = fp16(tanh(x)). 8 elems/thread.
// ---------------------------------------------------------------------------
__global__ void __launch_bounds__(256)
x_prep_kernel(const float* __restrict__ x, __half* __restrict__ x16,
              __half* __restrict__ cat, size_t n8)
{
    size_t i = (size_t)blockIdx.x * blockDim.x + threadIdx.x;
    if (i >= n8) return;
    size_t e = i * 8;
    float4 v0 = *(const float4*)(x + e);
    float4 v1 = *(const float4*)(x + e + 4);
    __half2 h0 = __floats2half2_rn(v0.x, v0.y);
    __half2 h1 = __floats2half2_rn(v0.z, v0.w);
    __half2 h2 = __floats2half2_rn(v1.x, v1.y);
    __half2 h3 = __floats2half2_rn(v1.z, v1.w);
    uint4 o;
    o.x = *(uint32_t*)&h0; o.y = *(uint32_t*)&h1;
    o.z = *(uint32_t*)&h2; o.w = *(uint32_t*)&h3;
    *(uint4*)(x16 + e) = o;

    __half2 t0 = __floats2half2_rn(tanhf(v0.x), tanhf(v0.y));
    __half2 t1 = __floats2half2_rn(tanhf(v0.z), tanhf(v0.w));
    __half2 t2 = __floats2half2_rn(tanhf(v1.x), tanhf(v1.y));
    __half2 t3 = __floats2half2_rn(tanhf(v1.z), tanhf(v1.w));
    uint4 t;
    t.x = *(uint32_t*)&t0; t.y = *(uint32_t*)&t1;
    t.z = *(uint32_t*)&t2; t.w = *(uint32_t*)&t3;
    size_t row = e >> 12;                 // / D_IN
    int col = (int)(e & (D_IN - 1));
    *(uint4*)(cat + row * CAT_DIM + Z_DIM + col) = t;
}

// ---------------------------------------------------------------------------
// fp32 -> fp16 (rn), 8 elems/thread (single tensor)
// ---------------------------------------------------------------------------
__global__ void __launch_bounds__(256)
f2h_kernel(const float* __restrict__ in, __half* __restrict__ out, size_t n8)
{
    size_t i = (size_t)blockIdx.x * blockDim.x + threadIdx.x;
    if (i >= n8) return;
    float4 v0 = *(const float4*)(in + i * 8);
    float4 v1 = *(const float4*)(in + i * 8 + 4);
    __half2 h0 = __floats2half2_rn(v0.x, v0.y);
    __half2 h1 = __floats2half2_rn(v0.z, v0.w);
    __half2 h2 = __floats2half2_rn(v1.x, v1.y);
    __half2 h3 = __floats2half2_rn(v1.z, v1.w);
    uint4 o;
    o.x = *(uint32_t*)&h0; o.y = *(uint32_t*)&h1;
    o.z = *(uint32_t*)&h2; o.w = *(uint32_t*)&h3;
    *(uint4*)(out + i * 8) = o;
}

// three same-size tensors in one launch
__global__ void __launch_bounds__(256)
f2h3_kernel(const float* __restrict__ i0, const float* __restrict__ i1,
            const float* __restrict__ i2, __half* __restrict__ o0,
            __half* __restrict__ o1, __half* __restrict__ o2, size_t n8)
{
    size_t i = (size_t)blockIdx.x * blockDim.x + threadIdx.x;
    if (i >= n8) return;
    const float* ins[3] = {i0, i1, i2};
    __half* outs[3] = {o0, o1, o2};
#pragma unroll
    for (int k = 0; k < 3; k++) {
        float4 v0 = *(const float4*)(ins[k] + i * 8);
        float4 v1 = *(const float4*)(ins[k] + i * 8 + 4);
        __half2 h0 = __floats2half2_rn(v0.x, v0.y);
        __half2 h1 = __floats2half2_rn(v0.z, v0.w);
        __half2 h2 = __floats2half2_rn(v1.x, v1.y);
        __half2 h3 = __floats2half2_rn(v1.z, v1.w);
        uint4 o;
        o.x = *(uint32_t*)&h0; o.y = *(uint32_t*)&h1;
        o.z = *(uint32_t*)&h2; o.w = *(uint32_t*)&h3;
        *(uint4*)(outs[k] + i * 8) = o;
    }
}

// ---------------------------------------------------------------------------
// LayerNorm (1024) + tanh, fp32 in -> fp16 out (feeds next GEMM).
// ---------------------------------------------------------------------------
__global__ void __launch_bounds__(256)
ln_tanh_kernel(const float* __restrict__ in, const float* __restrict__ gamma,
               const float* __restrict__ beta, __half* __restrict__ out)
{
    const int row = blockIdx.x;
    const int tid = threadIdx.x;
    const float* p = in + (size_t)row * Z_DIM;

    float4 v = *(const float4*)(p + tid * 4);

    __shared__ float red[8];
    float s = v.x + v.y + v.z + v.w;
#pragma unroll
    for (int o = 16; o > 0; o >>= 1) s += __shfl_down_sync(0xffffffffu, s, o);
    if ((tid & 31) == 0) red[tid >> 5] = s;
    __syncthreads();
    {
        float t = (tid < 8) ? red[tid] : 0.f;
#pragma unroll
        for (int o = 4; o > 0; o >>= 1) t += __shfl_down_sync(0xffu, t, o);
        if (tid == 0) red[0] = t;
    }
    __syncthreads();
    const float mean = red[0] * (1.0f / Z_DIM);
    __syncthreads();

    float d0 = v.x - mean, d1 = v.y - mean, d2 = v.z - mean, d3 = v.w - mean;
    float s2 = d0 * d0 + d1 * d1 + d2 * d2 + d3 * d3;
#pragma unroll
    for (int o = 16; o > 0; o >>= 1) s2 += __shfl_down_sync(0xffffffffu, s2, o);
    if ((tid & 31) == 0) red[tid >> 5] = s2;
    __syncthreads();
    {
        float t = (tid < 8) ? red[tid] : 0.f;
#pragma unroll
        for (int o = 4; o > 0; o >>= 1) t += __shfl_down_sync(0xffu, t, o);
        if (tid == 0) red[0] = t;
    }
    __syncthreads();
    const float rstd = rsqrtf(red[0] * (1.0f / Z_DIM) + LN_EPS);

    const int col = tid * 4;
    float4 g = *(const float4*)(gamma + col);
    float4 b = *(const float4*)(beta + col);
    __half2 h0 = __floats2half2_rn(tanhf(d0 * rstd * g.x + b.x),
                                   tanhf(d1 * rstd * g.y + b.y));
    __half2 h1 = __floats2half2_rn(tanhf(d2 * rstd * g.z + b.z),
                                   tanhf(d3 * rstd * g.w + b.w));
    uint2 o;
    o.x = *(uint32_t*)&h0; o.y = *(uint32_t*)&h1;
    *(uint2*)(out + (size_t)row * Z_DIM + col) = o;
}

// ---------------------------------------------------------------------------
// z-part of cat only: cat[:, :Z_DIM] = fp16(tanh(eps*std+mu)). 2 elems/thread.
// ---------------------------------------------------------------------------
__global__ void __launch_bounds__(256)
cat_z_kernel(const float* __restrict__ eps, const float* __restrict__ mu,
             const float* __restrict__ stdv, __half* __restrict__ cat)
{
    size_t idx = (size_t)blockIdx.x * blockDim.x + threadIdx.x;
    size_t total2 = (size_t)M_TOK * Z_DIM / 2;
    if (idx >= total2) return;
    size_t row = idx >> 9;                 // / (Z_DIM/2)
    int col = (int)(idx & 511) * 2;
    size_t zi = row * Z_DIM + col;
    float a = eps[zi] * stdv[zi] + mu[zi];
    float b = eps[zi + 1] * stdv[zi + 1] + mu[zi + 1];
    __half2 h = __floats2half2_rn(tanhf(a), tanhf(b));
    *(uint32_t*)(cat + row * CAT_DIM + col) = *(uint32_t*)&h;
}

// ---------------------------------------------------------------------------
extern "C" void kernel_launch(void* const* d_in, const int* in_sizes, int n_in,
                              void* d_out, int out_size)
{
    const float* x   = (const float*)d_in[0];
    const float* eps = (const float*)d_in[1];
    const float* W1  = (const float*)d_in[2];
    const float* b1  = (const float*)d_in[3];
    const float* g1  = (const float*)d_in[4];
    const float* be1 = (const float*)d_in[5];
    const float* W2  = (const float*)d_in[6];
    const float* b2  = (const float*)d_in[7];
    const float* g2  = (const float*)d_in[8];
    const float* be2 = (const float*)d_in[9];
    const float* Wmu = (const float*)d_in[10];
    const float* bmu = (const float*)d_in[11];
    const float* Wls = (const float*)d_in[12];
    const float* bls = (const float*)d_in[13];
    const float* Wzw = (const float*)d_in[14];
    const float* bzw = (const float*)d_in[15];

    float* out_p = (float*)d_out;
    float* mu_p  = out_p + MU_OFF;
    float* std_p = out_p + STD_OFF;

    float*  c_p;   cudaGetSymbolAddress((void**)&c_p,   g_c);
    __half* h_p;   cudaGetSymbolAddress((void**)&h_p,   g_h);
    __half* cat_p; cudaGetSymbolAddress((void**)&cat_p, g_cat);
    __half* x16_p; cudaGetSymbolAddress((void**)&x16_p, g_x16);
    __half* w_p;   cudaGetSymbolAddress((void**)&w_p,   g_w16);

    dim3 blk(256);

    // 0) convert operands: x (+ tanh(x) into cat), W1, {W2,Wmu,Wls}, Wzw
    {
        size_t nx8 = (size_t)M_TOK * D_IN / 8;
        x_prep_kernel<<<(unsigned)((nx8 + 255) / 256), blk>>>(x, x16_p, cat_p, nx8);
        size_t n1 = (size_t)Z_DIM * D_IN / 8;
        f2h_kernel<<<(unsigned)((n1 + 255) / 256), blk>>>(W1, w_p + W1_OFF, n1);
        size_t nz = (size_t)Z_DIM * Z_DIM / 8;
        f2h3_kernel<<<(unsigned)((nz + 255) / 256), blk>>>(
            W2, Wmu, Wls, w_p + W2_OFF, w_p + WMU_OFF, w_p + WLS_OFF, nz);
        size_t nw = (size_t)D_OUT * CAT_DIM / 8;
        f2h_kernel<<<(unsigned)((nw + 255) / 256), blk>>>(Wzw, w_p + WZW_OFF, nw);
    }

    // 1) c = x @ W1^T + b1
    gemm_f16_kernel<<<dim3(Z_DIM / 128, M_TOK / 128), blk>>>(
        x16_p, w_p + W1_OFF, b1, nullptr, c_p, nullptr, M_TOK, Z_DIM, D_IN, 0);
    // 2) h = tanh(LN(c))
    ln_tanh_kernel<<<M_TOK, blk>>>(c_p, g1, be1, h_p);
    // 3) c = h @ W2^T + b2
    gemm_f16_kernel<<<dim3(Z_DIM / 128, M_TOK / 128), blk>>>(
        h_p, w_p + W2_OFF, b2, nullptr, c_p, nullptr, M_TOK, Z_DIM, Z_DIM, 0);
    // 4) h = tanh(LN(c))
    ln_tanh_kernel<<<M_TOK, blk>>>(c_p, g2, be2, h_p);
    // 5+6) fused: [mu | std] = h @ [Wmu|Wls]^T  (std half gets exp(0.5*..))
    gemm_f16_kernel<<<dim3(2 * Z_DIM / 128, M_TOK / 128), blk>>>(
        h_p, w_p + WMU_OFF, bmu, bls, mu_p, std_p, M_TOK, 2 * Z_DIM, Z_DIM, 2);
    // 7) cat z-part (x-part already written by x_prep)
    {
        size_t total2 = (size_t)M_TOK * Z_DIM / 2;
        cat_z_kernel<<<(unsigned)((total2 + 255) / 256), blk>>>(eps, mu_p, std_p, cat_p);
    }
    // 8) out = cat @ Wzw^T + bzw
    gemm_f16_kernel<<<dim3(D_OUT / 128, M_TOK / 128), blk>>>(
        cat_p, w_p + WZW_OFF, bzw, nullptr, out_p, nullptr, M_TOK, D_OUT, CAT_DIM, 0);
}

// round 12
// speedup vs baseline: 1.1575x; 1.1575x over previous
#include <cuda_runtime.h>
#include <cuda_fp16.h>
#include <math.h>
#include <stdint.h>

// Problem constants
#define M_TOK   8192
#define D_IN    4096
#define Z_DIM   1024
#define D_OUT   4096
#define CAT_DIM 5120
#define LN_EPS  1e-5f

#define MU_OFF  (M_TOK * (size_t)D_OUT)
#define STD_OFF (MU_OFF + (size_t)M_TOK * Z_DIM)

// Scratch (device globals — allocation-free per harness rules)
__device__ __align__(256) float  g_c[(size_t)M_TOK * Z_DIM];      // pre-LN (fp32)
__device__ __align__(256) __half g_h[(size_t)M_TOK * Z_DIM];      // post LN+tanh (fp16)
__device__ __align__(256) __half g_cat[(size_t)M_TOK * CAT_DIM];  // tanh concat (fp16)
__device__ __align__(256) __half g_x16[(size_t)M_TOK * D_IN];     // x in fp16
// fp16 weights, packed: W1 | W2 | Wmu | Wls | Wzw (Wmu,Wls adjacent => fused)
#define W1_OFF  0
#define W2_OFF  4194304
#define WMU_OFF 5242880
#define WLS_OFF 6291456
#define WZW_OFF 7340032
#define W_TOTAL 28311552
__device__ __align__(256) __half g_w16[(size_t)W_TOTAL];

// ---------------------------------------------------------------------------
// PTX helpers
// ---------------------------------------------------------------------------
__device__ __forceinline__ void cp16(uint32_t dst, const void* src) {
    asm volatile("cp.async.cg.shared.global [%0], [%1], 16;\n" :: "r"(dst), "l"(src));
}
__device__ __forceinline__ void cp_commit() {
    asm volatile("cp.async.commit_group;\n" ::: "memory");
}
__device__ __forceinline__ void cp_wait2() {
    asm volatile("cp.async.wait_group 2;\n" ::: "memory");
}
__device__ __forceinline__ void ldsm4(uint32_t* r, uint32_t addr) {
    asm volatile("ldmatrix.sync.aligned.m8n8.x4.shared.b16 {%0,%1,%2,%3}, [%4];\n"
        : "=r"(r[0]), "=r"(r[1]), "=r"(r[2]), "=r"(r[3]) : "r"(addr));
}
__device__ __forceinline__ void mma_f16(float* d, const uint32_t* a, const uint32_t* b) {
    asm volatile(
        "mma.sync.aligned.m16n8k16.row.col.f32.f16.f16.f32 "
        "{%0,%1,%2,%3}, {%4,%5,%6,%7}, {%8,%9}, {%0,%1,%2,%3};\n"
        : "+f"(d[0]), "+f"(d[1]), "+f"(d[2]), "+f"(d[3])
        : "r"(a[0]), "r"(a[1]), "r"(a[2]), "r"(a[3]), "r"(b[0]), "r"(b[1]));
}

// ---------------------------------------------------------------------------
// fp16 tensor-core GEMM (R9-verified geometry):
// C[M,N](fp32) = A[M,K](fp16) * B[N,K]^T(fp16) + bias
// Block tile 256x128, BK=32 halfs, 4-stage cp.async, single sync per k-tile,
// 512 threads, 16 warps (4M x 4N), warp tile 64x32.
// smem/stage: A 16KB + B 8KB = 24KB; 4 stages = 96KB dynamic.
// Rows are 64B (32 halfs) = 4 x 16B chunks; swizzle chunk ^ ((row>>1)&3).
// mode 0: plain. mode 2: split N at Z_DIM -> C(+biasA) | exp(0.5*(v+biasB))->C2.
// ---------------------------------------------------------------------------
#define GBK 32
#define STAGE_BYTES 24576
#define B_OFF       16384
#define STAGES      4
#define GEMM_SMEM   (STAGES * STAGE_BYTES)    // 96 KB

__global__ void __launch_bounds__(512, 1)
gemm_f16_kernel(const __half* __restrict__ A, const __half* __restrict__ B,
                const float* __restrict__ biasA, const float* __restrict__ biasB,
                float* __restrict__ C, float* __restrict__ C2,
                int M, int N, int K, int mode)
{
    extern __shared__ __align__(128) char smem[];

    const int tid  = threadIdx.x;
    const int lane = tid & 31;
    const int warp = tid >> 5;
    const int warp_m = warp & 3;    // 4 M-warps (64 rows each)
    const int warp_n = warp >> 2;   // 4 N-warps (32 cols each)

    const int bm = blockIdx.y * 256;
    const int bn = blockIdx.x * 128;

    const uint32_t sm_base = (uint32_t)__cvta_generic_to_shared(smem);

    // ---- cp.async mapping
    const int a_row = tid >> 1;
    const int a_c0  = (tid & 1) * 2;
    const int a_swz = (a_row >> 1) & 3;
    const __half* Ag = A + (size_t)(bm + a_row) * K + a_c0 * 8;
    uint32_t a_dst[2];
#pragma unroll
    for (int i = 0; i < 2; i++)
        a_dst[i] = sm_base + (uint32_t)(a_row * 64 + (((a_c0 + i) ^ a_swz) << 4));
    const int b_row = tid >> 2;
    const int b_c   = tid & 3;
    const int b_swz = (b_row >> 1) & 3;
    const __half* Bg = B + (size_t)(bn + b_row) * K + b_c * 8;
    const uint32_t b_dst = sm_base + B_OFF +
        (uint32_t)(b_row * 64 + ((b_c ^ b_swz) << 4));

    // ---- ldmatrix address precompute
    const int sa   = (lane & 7) + ((lane >> 3) & 1) * 8;
    const int hiA  = (lane >> 4) & 1;
    const int aswz = (sa >> 1) & 3;
    uint32_t a_base[4];
#pragma unroll
    for (int mf = 0; mf < 4; mf++)
        a_base[mf] = sm_base + (uint32_t)(warp_m * 64 + mf * 16 + sa) * 64u;

    const int hiB  = (lane >> 3) & 1;
    const int nbr  = ((lane >> 4) & 1) * 8 + (lane & 7);
    const int bswz = (nbr >> 1) & 3;
    uint32_t b_base[2];
#pragma unroll
    for (int p = 0; p < 2; p++)
        b_base[p] = sm_base + B_OFF + (uint32_t)(warp_n * 32 + p * 16 + nbr) * 64u;

    // ---- epilogue routing (split boundary Z_DIM is 128-aligned)
    const float* bp = biasA;
    float* Cp = C;
    int cadj = 0, effN = N, emode = 0;
    if (mode == 2) {
        effN = Z_DIM;
        if (bn >= Z_DIM) { bp = biasB; Cp = C2; cadj = Z_DIM; emode = 1; }
    }

    float bias2[4][2];
#pragma unroll
    for (int nf = 0; nf < 4; nf++) {
        int col = bn - cadj + warp_n * 32 + nf * 8 + (lane & 3) * 2;
        bias2[nf][0] = __ldg(bp + col);
        bias2[nf][1] = __ldg(bp + col + 1);
    }

    float acc[4][4][4];
#pragma unroll
    for (int mf = 0; mf < 4; mf++)
#pragma unroll
        for (int nf = 0; nf < 4; nf++)
#pragma unroll
            for (int r = 0; r < 4; r++) acc[mf][nf][r] = 0.f;

    const int KT = K / GBK;

    // ---- prologue: prefetch stages 0..2 (3 commit groups)
#pragma unroll
    for (int s = 0; s < STAGES - 1; s++) {
        if (s < KT) {
            const __half* ap = Ag + s * GBK;
            const __half* bq = Bg + s * GBK;
            uint32_t so = (uint32_t)s * STAGE_BYTES;
            cp16(a_dst[0] + so, ap);
            cp16(a_dst[1] + so, ap + 8);
            cp16(b_dst + so, bq);
        }
        cp_commit();
    }

    // ---- main loop: ONE __syncthreads per k-tile
    for (int kt = 0; kt < KT; kt++) {
        cp_wait2();            // stage kt complete (<=2 groups pending)
        __syncthreads();       // also guarantees stage kt-1 compute finished

        // issue stage kt+3 into slot (kt+3)&3 (= stage kt-1's slot; safe per sync)
        {
            int nxt = kt + (STAGES - 1);
            if (nxt < KT) {
                int sn = nxt & (STAGES - 1);
                const __half* ap = Ag + nxt * GBK;
                const __half* bq = Bg + nxt * GBK;
                uint32_t so = (uint32_t)sn * STAGE_BYTES;
                cp16(a_dst[0] + so, ap);
                cp16(a_dst[1] + so, ap + 8);
                cp16(b_dst + so, bq);
            }
            cp_commit();
        }

        const uint32_t so = (uint32_t)(kt & (STAGES - 1)) * STAGE_BYTES;
#pragma unroll
        for (int kk = 0; kk < 2; kk++) {   // two k16 slices per BK=32
            uint32_t a[4][4];
#pragma unroll
            for (int mf = 0; mf < 4; mf++)
                ldsm4(a[mf], a_base[mf] + so + (uint32_t)(((kk * 2 + hiA) ^ aswz) << 4));
            uint32_t b[4][2];
#pragma unroll
            for (int p = 0; p < 2; p++) {
                uint32_t r[4];
                ldsm4(r, b_base[p] + so + (uint32_t)(((kk * 2 + hiB) ^ bswz) << 4));
                b[2 * p][0] = r[0]; b[2 * p][1] = r[1];
                b[2 * p + 1][0] = r[2]; b[2 * p + 1][1] = r[3];
            }
#pragma unroll
            for (int mf = 0; mf < 4; mf++)
#pragma unroll
                for (int nf = 0; nf < 4; nf++)
                    mma_f16(acc[mf][nf], a[mf], b[nf]);
        }
    }

    // ---- epilogue (fp32 out)
#pragma unroll
    for (int mf = 0; mf < 4; mf++) {
        int r0 = bm + warp_m * 64 + mf * 16 + (lane >> 2);
#pragma unroll
        for (int nf = 0; nf < 4; nf++) {
            int col = bn - cadj + warp_n * 32 + nf * 8 + (lane & 3) * 2;
            float v0 = acc[mf][nf][0] + bias2[nf][0];
            float v1 = acc[mf][nf][1] + bias2[nf][1];
            float v2 = acc[mf][nf][2] + bias2[nf][0];
            float v3 = acc[mf][nf][3] + bias2[nf][1];
            if (emode == 1) {
                v0 = expf(0.5f * v0); v1 = expf(0.5f * v1);
                v2 = expf(0.5f * v2); v3 = expf(0.5f * v3);
            }
            *(float2*)(Cp + (size_t)r0 * effN + col) = make_float2(v0, v1);
            *(float2*)(Cp + (size_t)(r0 + 8) * effN + col) = make_float2(v2, v3);
        }
    }
}

// ---------------------------------------------------------------------------
// x prep: x16 = fp16(x) AND cat[:,Z_DIM:] = fp16(tanh(x)). 8 elems/thread.
// ---------------------------------------------------------------------------
__global__ void __launch_bounds__(256)
x_prep_kernel(const float* __restrict__ x, __half* __restrict__ x16,
              __half* __restrict__ cat, size_t n8)
{
    size_t i = (size_t)blockIdx.x * blockDim.x + threadIdx.x;
    if (i >= n8) return;
    size_t e = i * 8;
    float4 v0 = *(const float4*)(x + e);
    float4 v1 = *(const float4*)(x + e + 4);
    __half2 h0 = __floats2half2_rn(v0.x, v0.y);
    __half2 h1 = __floats2half2_rn(v0.z, v0.w);
    __half2 h2 = __floats2half2_rn(v1.x, v1.y);
    __half2 h3 = __floats2half2_rn(v1.z, v1.w);
    uint4 o;
    o.x = *(uint32_t*)&h0; o.y = *(uint32_t*)&h1;
    o.z = *(uint32_t*)&h2; o.w = *(uint32_t*)&h3;
    *(uint4*)(x16 + e) = o;

    __half2 t0 = __floats2half2_rn(tanhf(v0.x), tanhf(v0.y));
    __half2 t1 = __floats2half2_rn(tanhf(v0.z), tanhf(v0.w));
    __half2 t2 = __floats2half2_rn(tanhf(v1.x), tanhf(v1.y));
    __half2 t3 = __floats2half2_rn(tanhf(v1.z), tanhf(v1.w));
    uint4 t;
    t.x = *(uint32_t*)&t0; t.y = *(uint32_t*)&t1;
    t.z = *(uint32_t*)&t2; t.w = *(uint32_t*)&t3;
    size_t row = e >> 12;                 // / D_IN
    int col = (int)(e & (D_IN - 1));
    *(uint4*)(cat + row * CAT_DIM + Z_DIM + col) = t;
}

// ---------------------------------------------------------------------------
// fp32 -> fp16 (rn), 8 elems/thread (single tensor)
// ---------------------------------------------------------------------------
__global__ void __launch_bounds__(256)
f2h_kernel(const float* __restrict__ in, __half* __restrict__ out, size_t n8)
{
    size_t i = (size_t)blockIdx.x * blockDim.x + threadIdx.x;
    if (i >= n8) return;
    float4 v0 = *(const float4*)(in + i * 8);
    float4 v1 = *(const float4*)(in + i * 8 + 4);
    __half2 h0 = __floats2half2_rn(v0.x, v0.y);
    __half2 h1 = __floats2half2_rn(v0.z, v0.w);
    __half2 h2 = __floats2half2_rn(v1.x, v1.y);
    __half2 h3 = __floats2half2_rn(v1.z, v1.w);
    uint4 o;
    o.x = *(uint32_t*)&h0; o.y = *(uint32_t*)&h1;
    o.z = *(uint32_t*)&h2; o.w = *(uint32_t*)&h3;
    *(uint4*)(out + i * 8) = o;
}

// three same-size tensors in one launch
__global__ void __launch_bounds__(256)
f2h3_kernel(const float* __restrict__ i0, const float* __restrict__ i1,
            const float* __restrict__ i2, __half* __restrict__ o0,
            __half* __restrict__ o1, __half* __restrict__ o2, size_t n8)
{
    size_t i = (size_t)blockIdx.x * blockDim.x + threadIdx.x;
    if (i >= n8) return;
    const float* ins[3] = {i0, i1, i2};
    __half* outs[3] = {o0, o1, o2};
#pragma unroll
    for (int k = 0; k < 3; k++) {
        float4 v0 = *(const float4*)(ins[k] + i * 8);
        float4 v1 = *(const float4*)(ins[k] + i * 8 + 4);
        __half2 h0 = __floats2half2_rn(v0.x, v0.y);
        __half2 h1 = __floats2half2_rn(v0.z, v0.w);
        __half2 h2 = __floats2half2_rn(v1.x, v1.y);
        __half2 h3 = __floats2half2_rn(v1.z, v1.w);
        uint4 o;
        o.x = *(uint32_t*)&h0; o.y = *(uint32_t*)&h1;
        o.z = *(uint32_t*)&h2; o.w = *(uint32_t*)&h3;
        *(uint4*)(outs[k] + i * 8) = o;
    }
}

// ---------------------------------------------------------------------------
// LayerNorm (1024) + tanh, fp32 in -> fp16 out (feeds next GEMM).
// ---------------------------------------------------------------------------
__global__ void __launch_bounds__(256)
ln_tanh_kernel(const float* __restrict__ in, const float* __restrict__ gamma,
               const float* __restrict__ beta, __half* __restrict__ out)
{
    const int row = blockIdx.x;
    const int tid = threadIdx.x;
    const float* p = in + (size_t)row * Z_DIM;

    float4 v = *(const float4*)(p + tid * 4);

    __shared__ float red[8];
    float s = v.x + v.y + v.z + v.w;
#pragma unroll
    for (int o = 16; o > 0; o >>= 1) s += __shfl_down_sync(0xffffffffu, s, o);
    if ((tid & 31) == 0) red[tid >> 5] = s;
    __syncthreads();
    {
        float t = (tid < 8) ? red[tid] : 0.f;
#pragma unroll
        for (int o = 4; o > 0; o >>= 1) t += __shfl_down_sync(0xffu, t, o);
        if (tid == 0) red[0] = t;
    }
    __syncthreads();
    const float mean = red[0] * (1.0f / Z_DIM);
    __syncthreads();

    float d0 = v.x - mean, d1 = v.y - mean, d2 = v.z - mean, d3 = v.w - mean;
    float s2 = d0 * d0 + d1 * d1 + d2 * d2 + d3 * d3;
#pragma unroll
    for (int o = 16; o > 0; o >>= 1) s2 += __shfl_down_sync(0xffffffffu, s2, o);
    if ((tid & 31) == 0) red[tid >> 5] = s2;
    __syncthreads();
    {
        float t = (tid < 8) ? red[tid] : 0.f;
#pragma unroll
        for (int o = 4; o > 0; o >>= 1) t += __shfl_down_sync(0xffu, t, o);
        if (tid == 0) red[0] = t;
    }
    __syncthreads();
    const float rstd = rsqrtf(red[0] * (1.0f / Z_DIM) + LN_EPS);

    const int col = tid * 4;
    float4 g = *(const float4*)(gamma + col);
    float4 b = *(const float4*)(beta + col);
    __half2 h0 = __floats2half2_rn(tanhf(d0 * rstd * g.x + b.x),
                                   tanhf(d1 * rstd * g.y + b.y));
    __half2 h1 = __floats2half2_rn(tanhf(d2 * rstd * g.z + b.z),
                                   tanhf(d3 * rstd * g.w + b.w));
    uint2 o;
    o.x = *(uint32_t*)&h0; o.y = *(uint32_t*)&h1;
    *(uint2*)(out + (size_t)row * Z_DIM + col) = o;
}

// ---------------------------------------------------------------------------
// z-part of cat only: cat[:, :Z_DIM] = fp16(tanh(eps*std+mu)). 2 elems/thread.
// ---------------------------------------------------------------------------
__global__ void __launch_bounds__(256)
cat_z_kernel(const float* __restrict__ eps, const float* __restrict__ mu,
             const float* __restrict__ stdv, __half* __restrict__ cat)
{
    size_t idx = (size_t)blockIdx.x * blockDim.x + threadIdx.x;
    size_t total2 = (size_t)M_TOK * Z_DIM / 2;
    if (idx >= total2) return;
    size_t row = idx >> 9;                 // / (Z_DIM/2)
    int col = (int)(idx & 511) * 2;
    size_t zi = row * Z_DIM + col;
    float a = eps[zi] * stdv[zi] + mu[zi];
    float b = eps[zi + 1] * stdv[zi + 1] + mu[zi + 1];
    __half2 h = __floats2half2_rn(tanhf(a), tanhf(b));
    *(uint32_t*)(cat + row * CAT_DIM + col) = *(uint32_t*)&h;
}

// ---------------------------------------------------------------------------
extern "C" void kernel_launch(void* const* d_in, const int* in_sizes, int n_in,
                              void* d_out, int out_size)
{
    const float* x   = (const float*)d_in[0];
    const float* eps = (const float*)d_in[1];
    const float* W1  = (const float*)d_in[2];
    const float* b1  = (const float*)d_in[3];
    const float* g1  = (const float*)d_in[4];
    const float* be1 = (const float*)d_in[5];
    const float* W2  = (const float*)d_in[6];
    const float* b2  = (const float*)d_in[7];
    const float* g2  = (const float*)d_in[8];
    const float* be2 = (const float*)d_in[9];
    const float* Wmu = (const float*)d_in[10];
    const float* bmu = (const float*)d_in[11];
    const float* Wls = (const float*)d_in[12];
    const float* bls = (const float*)d_in[13];
    const float* Wzw = (const float*)d_in[14];
    const float* bzw = (const float*)d_in[15];

    float* out_p = (float*)d_out;
    float* mu_p  = out_p + MU_OFF;
    float* std_p = out_p + STD_OFF;

    float*  c_p;   cudaGetSymbolAddress((void**)&c_p,   g_c);
    __half* h_p;   cudaGetSymbolAddress((void**)&h_p,   g_h);
    __half* cat_p; cudaGetSymbolAddress((void**)&cat_p, g_cat);
    __half* x16_p; cudaGetSymbolAddress((void**)&x16_p, g_x16);
    __half* w_p;   cudaGetSymbolAddress((void**)&w_p,   g_w16);

    cudaFuncSetAttribute(gemm_f16_kernel,
                         cudaFuncAttributeMaxDynamicSharedMemorySize, GEMM_SMEM);

    dim3 blk(256);
    dim3 gblk(512);

    // 0) convert operands: x (+ tanh(x) into cat), W1, {W2,Wmu,Wls}, Wzw
    {
        size_t nx8 = (size_t)M_TOK * D_IN / 8;
        x_prep_kernel<<<(unsigned)((nx8 + 255) / 256), blk>>>(x, x16_p, cat_p, nx8);
        size_t n1 = (size_t)Z_DIM * D_IN / 8;
        f2h_kernel<<<(unsigned)((n1 + 255) / 256), blk>>>(W1, w_p + W1_OFF, n1);
        size_t nz = (size_t)Z_DIM * Z_DIM / 8;
        f2h3_kernel<<<(unsigned)((nz + 255) / 256), blk>>>(
            W2, Wmu, Wls, w_p + W2_OFF, w_p + WMU_OFF, w_p + WLS_OFF, nz);
        size_t nw = (size_t)D_OUT * CAT_DIM / 8;
        f2h_kernel<<<(unsigned)((nw + 255) / 256), blk>>>(Wzw, w_p + WZW_OFF, nw);
    }

    // 1) c = x @ W1^T + b1
    gemm_f16_kernel<<<dim3(Z_DIM / 128, M_TOK / 256), gblk, GEMM_SMEM>>>(
        x16_p, w_p + W1_OFF, b1, nullptr, c_p, nullptr, M_TOK, Z_DIM, D_IN, 0);
    // 2) h = tanh(LN(c))
    ln_tanh_kernel<<<M_TOK, blk>>>(c_p, g1, be1, h_p);
    // 3) c = h @ W2^T + b2
    gemm_f16_kernel<<<dim3(Z_DIM / 128, M_TOK / 256), gblk, GEMM_SMEM>>>(
        h_p, w_p + W2_OFF, b2, nullptr, c_p, nullptr, M_TOK, Z_DIM, Z_DIM, 0);
    // 4) h = tanh(LN(c))
    ln_tanh_kernel<<<M_TOK, blk>>>(c_p, g2, be2, h_p);
    // 5+6) fused: [mu | std] = h @ [Wmu|Wls]^T  (std half gets exp(0.5*..))
    gemm_f16_kernel<<<dim3(2 * Z_DIM / 128, M_TOK / 256), gblk, GEMM_SMEM>>>(
        h_p, w_p + WMU_OFF, bmu, bls, mu_p, std_p, M_TOK, 2 * Z_DIM, Z_DIM, 2);
    // 7) cat z-part (x-part already written by x_prep)
    {
        size_t total2 = (size_t)M_TOK * Z_DIM / 2;
        cat_z_kernel<<<(unsigned)((total2 + 255) / 256), blk>>>(eps, mu_p, std_p, cat_p);
    }
    // 8) out = cat @ Wzw^T + bzw
    gemm_f16_kernel<<<dim3(D_OUT / 128, M_TOK / 256), gblk, GEMM_SMEM>>>(
        cat_p, w_p + WZW_OFF, bzw, nullptr, out_p, nullptr, M_TOK, D_OUT, CAT_DIM, 0);
}

// round 13
// speedup vs baseline: 1.1648x; 1.0063x over previous
#include <cuda_runtime.h>
#include <cuda_fp16.h>
#include <math.h>
#include <stdint.h>

// Problem constants
#define M_TOK   8192
#define D_IN    4096
#define Z_DIM   1024
#define D_OUT   4096
#define CAT_DIM 5120
#define LN_EPS  1e-5f

#define MU_OFF  (M_TOK * (size_t)D_OUT)
#define STD_OFF (MU_OFF + (size_t)M_TOK * Z_DIM)

// Scratch (device globals — allocation-free per harness rules)
__device__ __align__(256) float  g_c[(size_t)M_TOK * Z_DIM];      // pre-LN (fp32)
__device__ __align__(256) __half g_h[(size_t)M_TOK * Z_DIM];      // post LN+tanh (fp16)
__device__ __align__(256) __half g_cat[(size_t)M_TOK * CAT_DIM];  // tanh concat (fp16)
__device__ __align__(256) __half g_x16[(size_t)M_TOK * D_IN];     // x in fp16
// fp16 weights, packed: W1 | W2 | Wmu | Wls | Wzw (Wmu,Wls adjacent => fused)
#define W1_OFF  0
#define W2_OFF  4194304
#define WMU_OFF 5242880
#define WLS_OFF 6291456
#define WZW_OFF 7340032
#define W_TOTAL 28311552
__device__ __align__(256) __half g_w16[(size_t)W_TOTAL];

// ---------------------------------------------------------------------------
// PTX helpers
// ---------------------------------------------------------------------------
__device__ __forceinline__ void cp16(uint32_t dst, const void* src) {
    asm volatile("cp.async.cg.shared.global [%0], [%1], 16;\n" :: "r"(dst), "l"(src));
}
__device__ __forceinline__ void cp_commit() {
    asm volatile("cp.async.commit_group;\n" ::: "memory");
}
__device__ __forceinline__ void cp_wait2() {
    asm volatile("cp.async.wait_group 2;\n" ::: "memory");
}
__device__ __forceinline__ void ldsm4(uint32_t* r, uint32_t addr) {
    asm volatile("ldmatrix.sync.aligned.m8n8.x4.shared.b16 {%0,%1,%2,%3}, [%4];\n"
        : "=r"(r[0]), "=r"(r[1]), "=r"(r[2]), "=r"(r[3]) : "r"(addr));
}
__device__ __forceinline__ void mma_f16(float* d, const uint32_t* a, const uint32_t* b) {
    asm volatile(
        "mma.sync.aligned.m16n8k16.row.col.f32.f16.f16.f32 "
        "{%0,%1,%2,%3}, {%4,%5,%6,%7}, {%8,%9}, {%0,%1,%2,%3};\n"
        : "+f"(d[0]), "+f"(d[1]), "+f"(d[2]), "+f"(d[3])
        : "r"(a[0]), "r"(a[1]), "r"(a[2]), "r"(a[3]), "r"(b[0]), "r"(b[1]));
}

// ---------------------------------------------------------------------------
// fp16 tensor-core GEMM (R9/R12-verified geometry — do not touch):
// C[M,N](fp32) = A[M,K](fp16) * B[N,K]^T(fp16) + bias
// Block tile 256x128, BK=32 halfs, 4-stage cp.async, single sync per k-tile,
// 512 threads, 16 warps (4M x 4N), warp tile 64x32.
// mode 0: plain. mode 2: split N at Z_DIM -> C(+biasA) | exp(0.5*(v+biasB))->C2.
// ---------------------------------------------------------------------------
#define GBK 32
#define STAGE_BYTES 24576
#define B_OFF       16384
#define STAGES      4
#define GEMM_SMEM   (STAGES * STAGE_BYTES)    // 96 KB

__global__ void __launch_bounds__(512, 1)
gemm_f16_kernel(const __half* __restrict__ A, const __half* __restrict__ B,
                const float* __restrict__ biasA, const float* __restrict__ biasB,
                float* __restrict__ C, float* __restrict__ C2,
                int M, int N, int K, int mode)
{
    extern __shared__ __align__(128) char smem[];

    const int tid  = threadIdx.x;
    const int lane = tid & 31;
    const int warp = tid >> 5;
    const int warp_m = warp & 3;
    const int warp_n = warp >> 2;

    const int bm = blockIdx.y * 256;
    const int bn = blockIdx.x * 128;

    const uint32_t sm_base = (uint32_t)__cvta_generic_to_shared(smem);

    const int a_row = tid >> 1;
    const int a_c0  = (tid & 1) * 2;
    const int a_swz = (a_row >> 1) & 3;
    const __half* Ag = A + (size_t)(bm + a_row) * K + a_c0 * 8;
    uint32_t a_dst[2];
#pragma unroll
    for (int i = 0; i < 2; i++)
        a_dst[i] = sm_base + (uint32_t)(a_row * 64 + (((a_c0 + i) ^ a_swz) << 4));
    const int b_row = tid >> 2;
    const int b_c   = tid & 3;
    const int b_swz = (b_row >> 1) & 3;
    const __half* Bg = B + (size_t)(bn + b_row) * K + b_c * 8;
    const uint32_t b_dst = sm_base + B_OFF +
        (uint32_t)(b_row * 64 + ((b_c ^ b_swz) << 4));

    const int sa   = (lane & 7) + ((lane >> 3) & 1) * 8;
    const int hiA  = (lane >> 4) & 1;
    const int aswz = (sa >> 1) & 3;
    uint32_t a_base[4];
#pragma unroll
    for (int mf = 0; mf < 4; mf++)
        a_base[mf] = sm_base + (uint32_t)(warp_m * 64 + mf * 16 + sa) * 64u;

    const int hiB  = (lane >> 3) & 1;
    const int nbr  = ((lane >> 4) & 1) * 8 + (lane & 7);
    const int bswz = (nbr >> 1) & 3;
    uint32_t b_base[2];
#pragma unroll
    for (int p = 0; p < 2; p++)
        b_base[p] = sm_base + B_OFF + (uint32_t)(warp_n * 32 + p * 16 + nbr) * 64u;

    const float* bp = biasA;
    float* Cp = C;
    int cadj = 0, effN = N, emode = 0;
    if (mode == 2) {
        effN = Z_DIM;
        if (bn >= Z_DIM) { bp = biasB; Cp = C2; cadj = Z_DIM; emode = 1; }
    }

    float bias2[4][2];
#pragma unroll
    for (int nf = 0; nf < 4; nf++) {
        int col = bn - cadj + warp_n * 32 + nf * 8 + (lane & 3) * 2;
        bias2[nf][0] = __ldg(bp + col);
        bias2[nf][1] = __ldg(bp + col + 1);
    }

    float acc[4][4][4];
#pragma unroll
    for (int mf = 0; mf < 4; mf++)
#pragma unroll
        for (int nf = 0; nf < 4; nf++)
#pragma unroll
            for (int r = 0; r < 4; r++) acc[mf][nf][r] = 0.f;

    const int KT = K / GBK;

#pragma unroll
    for (int s = 0; s < STAGES - 1; s++) {
        if (s < KT) {
            const __half* ap = Ag + s * GBK;
            const __half* bq = Bg + s * GBK;
            uint32_t so = (uint32_t)s * STAGE_BYTES;
            cp16(a_dst[0] + so, ap);
            cp16(a_dst[1] + so, ap + 8);
            cp16(b_dst + so, bq);
        }
        cp_commit();
    }

    for (int kt = 0; kt < KT; kt++) {
        cp_wait2();
        __syncthreads();

        {
            int nxt = kt + (STAGES - 1);
            if (nxt < KT) {
                int sn = nxt & (STAGES - 1);
                const __half* ap = Ag + nxt * GBK;
                const __half* bq = Bg + nxt * GBK;
                uint32_t so = (uint32_t)sn * STAGE_BYTES;
                cp16(a_dst[0] + so, ap);
                cp16(a_dst[1] + so, ap + 8);
                cp16(b_dst + so, bq);
            }
            cp_commit();
        }

        const uint32_t so = (uint32_t)(kt & (STAGES - 1)) * STAGE_BYTES;
#pragma unroll
        for (int kk = 0; kk < 2; kk++) {
            uint32_t a[4][4];
#pragma unroll
            for (int mf = 0; mf < 4; mf++)
                ldsm4(a[mf], a_base[mf] + so + (uint32_t)(((kk * 2 + hiA) ^ aswz) << 4));
            uint32_t b[4][2];
#pragma unroll
            for (int p = 0; p < 2; p++) {
                uint32_t r[4];
                ldsm4(r, b_base[p] + so + (uint32_t)(((kk * 2 + hiB) ^ bswz) << 4));
                b[2 * p][0] = r[0]; b[2 * p][1] = r[1];
                b[2 * p + 1][0] = r[2]; b[2 * p + 1][1] = r[3];
            }
#pragma unroll
            for (int mf = 0; mf < 4; mf++)
#pragma unroll
                for (int nf = 0; nf < 4; nf++)
                    mma_f16(acc[mf][nf], a[mf], b[nf]);
        }
    }

#pragma unroll
    for (int mf = 0; mf < 4; mf++) {
        int r0 = bm + warp_m * 64 + mf * 16 + (lane >> 2);
#pragma unroll
        for (int nf = 0; nf < 4; nf++) {
            int col = bn - cadj + warp_n * 32 + nf * 8 + (lane & 3) * 2;
            float v0 = acc[mf][nf][0] + bias2[nf][0];
            float v1 = acc[mf][nf][1] + bias2[nf][1];
            float v2 = acc[mf][nf][2] + bias2[nf][0];
            float v3 = acc[mf][nf][3] + bias2[nf][1];
            if (emode == 1) {
                v0 = expf(0.5f * v0); v1 = expf(0.5f * v1);
                v2 = expf(0.5f * v2); v3 = expf(0.5f * v3);
            }
            *(float2*)(Cp + (size_t)r0 * effN + col) = make_float2(v0, v1);
            *(float2*)(Cp + (size_t)(r0 + 8) * effN + col) = make_float2(v2, v3);
        }
    }
}

// ---------------------------------------------------------------------------
// x prep: x16 = fp16(x) AND cat[:,Z_DIM:] = fp16(tanh(x)). 8 elems/thread.
// ---------------------------------------------------------------------------
__global__ void __launch_bounds__(256)
x_prep_kernel(const float* __restrict__ x, __half* __restrict__ x16,
              __half* __restrict__ cat, size_t n8)
{
    size_t i = (size_t)blockIdx.x * blockDim.x + threadIdx.x;
    if (i >= n8) return;
    size_t e = i * 8;
    float4 v0 = *(const float4*)(x + e);
    float4 v1 = *(const float4*)(x + e + 4);
    __half2 h0 = __floats2half2_rn(v0.x, v0.y);
    __half2 h1 = __floats2half2_rn(v0.z, v0.w);
    __half2 h2 = __floats2half2_rn(v1.x, v1.y);
    __half2 h3 = __floats2half2_rn(v1.z, v1.w);
    uint4 o;
    o.x = *(uint32_t*)&h0; o.y = *(uint32_t*)&h1;
    o.z = *(uint32_t*)&h2; o.w = *(uint32_t*)&h3;
    *(uint4*)(x16 + e) = o;

    __half2 t0 = __floats2half2_rn(tanhf(v0.x), tanhf(v0.y));
    __half2 t1 = __floats2half2_rn(tanhf(v0.z), tanhf(v0.w));
    __half2 t2 = __floats2half2_rn(tanhf(v1.x), tanhf(v1.y));
    __half2 t3 = __floats2half2_rn(tanhf(v1.z), tanhf(v1.w));
    uint4 t;
    t.x = *(uint32_t*)&t0; t.y = *(uint32_t*)&t1;
    t.z = *(uint32_t*)&t2; t.w = *(uint32_t*)&t3;
    size_t row = e >> 12;                 // / D_IN
    int col = (int)(e & (D_IN - 1));
    *(uint4*)(cat + row * CAT_DIM + Z_DIM + col) = t;
}

// ---------------------------------------------------------------------------
// Segmented weight convert: one launch handles W1|W2|Wmu|Wls|Wzw (fp32->fp16).
// Block ranges (256 thr x 8 elems = 2048 elems/block):
//   W1  : blocks [0,     2048)   (4,194,304 elems)
//   W2  : blocks [2048,  2560)   (1,048,576)
//   Wmu : blocks [2560,  3072)
//   Wls : blocks [3072,  3584)
//   Wzw : blocks [3584, 13824)   (20,971,520)
// ---------------------------------------------------------------------------
#define WCVT_BLOCKS 13824

__global__ void __launch_bounds__(256)
wcvt_kernel(const float* __restrict__ W1, const float* __restrict__ W2,
            const float* __restrict__ Wmu, const float* __restrict__ Wls,
            const float* __restrict__ Wzw, __half* __restrict__ w16)
{
    int bid = blockIdx.x;
    const float* src;
    __half* dst;
    int lb;
    if (bid < 2048)      { src = W1;  dst = w16 + W1_OFF;  lb = bid; }
    else if (bid < 2560) { src = W2;  dst = w16 + W2_OFF;  lb = bid - 2048; }
    else if (bid < 3072) { src = Wmu; dst = w16 + WMU_OFF; lb = bid - 2560; }
    else if (bid < 3584) { src = Wls; dst = w16 + WLS_OFF; lb = bid - 3072; }
    else                 { src = Wzw; dst = w16 + WZW_OFF; lb = bid - 3584; }

    size_t e = ((size_t)lb * 256 + threadIdx.x) * 8;
    float4 v0 = *(const float4*)(src + e);
    float4 v1 = *(const float4*)(src + e + 4);
    __half2 h0 = __floats2half2_rn(v0.x, v0.y);
    __half2 h1 = __floats2half2_rn(v0.z, v0.w);
    __half2 h2 = __floats2half2_rn(v1.x, v1.y);
    __half2 h3 = __floats2half2_rn(v1.z, v1.w);
    uint4 o;
    o.x = *(uint32_t*)&h0; o.y = *(uint32_t*)&h1;
    o.z = *(uint32_t*)&h2; o.w = *(uint32_t*)&h3;
    *(uint4*)(dst + e) = o;
}

// ---------------------------------------------------------------------------
// LayerNorm (1024) + tanh, single-pass (E[x^2]-mu^2), fp32 in -> fp16 out.
// ---------------------------------------------------------------------------
__global__ void __launch_bounds__(256)
ln_tanh_kernel(const float* __restrict__ in, const float* __restrict__ gamma,
               const float* __restrict__ beta, __half* __restrict__ out)
{
    const int row = blockIdx.x;
    const int tid = threadIdx.x;
    const float* p = in + (size_t)row * Z_DIM;

    float4 v = *(const float4*)(p + tid * 4);

    float s1 = v.x + v.y + v.z + v.w;
    float s2 = v.x * v.x + v.y * v.y + v.z * v.z + v.w * v.w;

    __shared__ float red1[8], red2[8];
#pragma unroll
    for (int o = 16; o > 0; o >>= 1) {
        s1 += __shfl_down_sync(0xffffffffu, s1, o);
        s2 += __shfl_down_sync(0xffffffffu, s2, o);
    }
    if ((tid & 31) == 0) { red1[tid >> 5] = s1; red2[tid >> 5] = s2; }
    __syncthreads();
    {
        float t1 = (tid < 8) ? red1[tid] : 0.f;
        float t2 = (tid < 8) ? red2[tid] : 0.f;
#pragma unroll
        for (int o = 4; o > 0; o >>= 1) {
            t1 += __shfl_down_sync(0xffu, t1, o);
            t2 += __shfl_down_sync(0xffu, t2, o);
        }
        if (tid == 0) { red1[0] = t1; red2[0] = t2; }
    }
    __syncthreads();
    const float mean = red1[0] * (1.0f / Z_DIM);
    const float var  = red2[0] * (1.0f / Z_DIM) - mean * mean;
    const float rstd = rsqrtf(var + LN_EPS);

    const int col = tid * 4;
    float4 g = *(const float4*)(gamma + col);
    float4 b = *(const float4*)(beta + col);
    float d0 = v.x - mean, d1 = v.y - mean, d2 = v.z - mean, d3 = v.w - mean;
    __half2 h0 = __floats2half2_rn(tanhf(d0 * rstd * g.x + b.x),
                                   tanhf(d1 * rstd * g.y + b.y));
    __half2 h1 = __floats2half2_rn(tanhf(d2 * rstd * g.z + b.z),
                                   tanhf(d3 * rstd * g.w + b.w));
    uint2 o;
    o.x = *(uint32_t*)&h0; o.y = *(uint32_t*)&h1;
    *(uint2*)(out + (size_t)row * Z_DIM + col) = o;
}

// ---------------------------------------------------------------------------
// z-part of cat only: cat[:, :Z_DIM] = fp16(tanh(eps*std+mu)). 2 elems/thread.
// ---------------------------------------------------------------------------
__global__ void __launch_bounds__(256)
cat_z_kernel(const float* __restrict__ eps, const float* __restrict__ mu,
             const float* __restrict__ stdv, __half* __restrict__ cat)
{
    size_t idx = (size_t)blockIdx.x * blockDim.x + threadIdx.x;
    size_t total2 = (size_t)M_TOK * Z_DIM / 2;
    if (idx >= total2) return;
    size_t row = idx >> 9;                 // / (Z_DIM/2)
    int col = (int)(idx & 511) * 2;
    size_t zi = row * Z_DIM + col;
    float a = eps[zi] * stdv[zi] + mu[zi];
    float b = eps[zi + 1] * stdv[zi + 1] + mu[zi + 1];
    __half2 h = __floats2half2_rn(tanhf(a), tanhf(b));
    *(uint32_t*)(cat + row * CAT_DIM + col) = *(uint32_t*)&h;
}

// ---------------------------------------------------------------------------
extern "C" void kernel_launch(void* const* d_in, const int* in_sizes, int n_in,
                              void* d_out, int out_size)
{
    const float* x   = (const float*)d_in[0];
    const float* eps = (const float*)d_in[1];
    const float* W1  = (const float*)d_in[2];
    const float* b1  = (const float*)d_in[3];
    const float* g1  = (const float*)d_in[4];
    const float* be1 = (const float*)d_in[5];
    const float* W2  = (const float*)d_in[6];
    const float* b2  = (const float*)d_in[7];
    const float* g2  = (const float*)d_in[8];
    const float* be2 = (const float*)d_in[9];
    const float* Wmu = (const float*)d_in[10];
    const float* bmu = (const float*)d_in[11];
    const float* Wls = (const float*)d_in[12];
    const float* bls = (const float*)d_in[13];
    const float* Wzw = (const float*)d_in[14];
    const float* bzw = (const float*)d_in[15];

    float* out_p = (float*)d_out;
    float* mu_p  = out_p + MU_OFF;
    float* std_p = out_p + STD_OFF;

    float*  c_p;   cudaGetSymbolAddress((void**)&c_p,   g_c);
    __half* h_p;   cudaGetSymbolAddress((void**)&h_p,   g_h);
    __half* cat_p; cudaGetSymbolAddress((void**)&cat_p, g_cat);
    __half* x16_p; cudaGetSymbolAddress((void**)&x16_p, g_x16);
    __half* w_p;   cudaGetSymbolAddress((void**)&w_p,   g_w16);

    cudaFuncSetAttribute(gemm_f16_kernel,
                         cudaFuncAttributeMaxDynamicSharedMemorySize, GEMM_SMEM);

    dim3 blk(256);
    dim3 gblk(512);

    // 0) converts: x (+ tanh(x) into cat) ; all five weights in ONE launch
    {
        size_t nx8 = (size_t)M_TOK * D_IN / 8;
        x_prep_kernel<<<(unsigned)((nx8 + 255) / 256), blk>>>(x, x16_p, cat_p, nx8);
        wcvt_kernel<<<WCVT_BLOCKS, blk>>>(W1, W2, Wmu, Wls, Wzw, w_p);
    }

    // 1) c = x @ W1^T + b1
    gemm_f16_kernel<<<dim3(Z_DIM / 128, M_TOK / 256), gblk, GEMM_SMEM>>>(
        x16_p, w_p + W1_OFF, b1, nullptr, c_p, nullptr, M_TOK, Z_DIM, D_IN, 0);
    // 2) h = tanh(LN(c))
    ln_tanh_kernel<<<M_TOK, blk>>>(c_p, g1, be1, h_p);
    // 3) c = h @ W2^T + b2
    gemm_f16_kernel<<<dim3(Z_DIM / 128, M_TOK / 256), gblk, GEMM_SMEM>>>(
        h_p, w_p + W2_OFF, b2, nullptr, c_p, nullptr, M_TOK, Z_DIM, Z_DIM, 0);
    // 4) h = tanh(LN(c))
    ln_tanh_kernel<<<M_TOK, blk>>>(c_p, g2, be2, h_p);
    // 5+6) fused: [mu | std] = h @ [Wmu|Wls]^T  (std half gets exp(0.5*..))
    gemm_f16_kernel<<<dim3(2 * Z_DIM / 128, M_TOK / 256), gblk, GEMM_SMEM>>>(
        h_p, w_p + WMU_OFF, bmu, bls, mu_p, std_p, M_TOK, 2 * Z_DIM, Z_DIM, 2);
    // 7) cat z-part (x-part already written by x_prep)
    {
        size_t total2 = (size_t)M_TOK * Z_DIM / 2;
        cat_z_kernel<<<(unsigned)((total2 + 255) / 256), blk>>>(eps, mu_p, std_p, cat_p);
    }
    // 8) out = cat @ Wzw^T + bzw
    gemm_f16_kernel<<<dim3(D_OUT / 128, M_TOK / 256), gblk, GEMM_SMEM>>>(
        cat_p, w_p + WZW_OFF, bzw, nullptr, out_p, nullptr, M_TOK, D_OUT, CAT_DIM, 0);
}